// round 16
// baseline (speedup 1.0000x reference)
#include <cuda_runtime.h>
#include <cuda_fp16.h>
#include <cstdint>
#include <math.h>

#define BB 8
#define NN 2048
#define NSPLIT 8

typedef __half hf;

// ================= scratch (device globals; allocation-free) =================
__device__ float g_L   [BB*(size_t)NN*NN];
__device__ float g_sq  [BB*NN];
__device__ float g_dinv[BB*NN];
__device__ float g_X0  [BB*NN*22];
__device__ float g_Ta  [BB*NN*512];
__device__ float g_Tb  [BB*NN*512];      // conv1 Tall [M, 512]
__device__ float g_pre [BB*NN*1024];
__device__ float g_act0[BB*NN*128];
__device__ float g_skip[BB*NN*512];
__device__ float g_act2[BB*NN*1024];     // conv2 Tall, then relu output
__device__ float g_fc0 [BB*NN*512];
__device__ float g_fc1 [BB*NN*128];
__device__ float g_part[(size_t)NSPLIT*BB*NN*24];

// fp16 split buffers (2 terms)
__device__ hf g_LS0[BB*(size_t)NN*NN];
__device__ hf g_LS1[BB*(size_t)NN*NN];
__device__ hf g_RS0[BB*(size_t)NN*1024];
__device__ hf g_RS1[BB*(size_t)NN*1024];
__device__ hf g_TS0[BB*(size_t)512*NN];
__device__ hf g_TS1[BB*(size_t)512*NN];
__device__ hf g_SK0[BB*(size_t)NN*512];
__device__ hf g_SK1[BB*(size_t)NN*512];
#define WT_TOTAL 2580480
__device__ hf g_WT0[WT_TOTAL];
__device__ hf g_WT1[WT_TOTAL];

// ================= helpers =================
__device__ __forceinline__ uint32_t smem_u32(const void* p){
    uint32_t a;
    asm("{ .reg .u64 t; cvta.to.shared.u64 t, %1; cvt.u32.u64 %0, t; }" : "=r"(a) : "l"(p));
    return a;
}
__device__ __forceinline__ void ldmx4(uint32_t* r, uint32_t a){
    asm volatile("ldmatrix.sync.aligned.m8n8.x4.shared.b16 {%0,%1,%2,%3}, [%4];"
        : "=r"(r[0]),"=r"(r[1]),"=r"(r[2]),"=r"(r[3]) : "r"(a));
}
__device__ __forceinline__ void mma16816(float* d, const uint32_t* a, uint32_t b0, uint32_t b1){
    asm volatile("mma.sync.aligned.m16n8k16.row.col.f32.f16.f16.f32 "
        "{%0,%1,%2,%3}, {%4,%5,%6,%7}, {%8,%9}, {%0,%1,%2,%3};"
        : "+f"(d[0]),"+f"(d[1]),"+f"(d[2]),"+f"(d[3])
        : "r"(a[0]),"r"(a[1]),"r"(a[2]),"r"(a[3]), "r"(b0),"r"(b1));
}
__device__ __forceinline__ void cpasync16(uint32_t dst, const void* src){
    asm volatile("cp.async.cg.shared.global [%0], [%1], 16;" :: "r"(dst), "l"(src));
}
#define CP_COMMIT() asm volatile("cp.async.commit_group;" ::: "memory")
#define CP_WAIT1()  asm volatile("cp.async.wait_group 1;" ::: "memory")
#define CP_WAIT0()  asm volatile("cp.async.wait_group 0;" ::: "memory")

// f32x2 packed fp32 (for lx22 path)
__device__ __forceinline__ unsigned long long pk2(float x) {
    unsigned long long r; unsigned xi = __float_as_uint(x);
    asm("mov.b64 %0, {%1, %1};" : "=l"(r) : "r"(xi));
    return r;
}
__device__ __forceinline__ void fma2(unsigned long long& d, unsigned long long a, unsigned long long b) {
    asm("fma.rn.f32x2 %0, %1, %2, %0;" : "+l"(d) : "l"(a), "l"(b));
}
__device__ __forceinline__ float lo32(unsigned long long v){ return __uint_as_float((unsigned)v); }
__device__ __forceinline__ float hi32(unsigned long long v){ return __uint_as_float((unsigned)(v>>32)); }

// fp16x2 split: x = h0 + h1 + O(2^-22 x)
__device__ __forceinline__ void hsplit(float x, unsigned short& s0, unsigned short& s1)
{
    __half h0 = __float2half_rn(x);
    float r = x - __half2float(h0);
    __half h1 = __float2half_rn(r);
    s0 = __half_as_ushort(h0);
    s1 = __half_as_ushort(h1);
}

// ================= mma.sync fp16x2 GEMM, cp.async double-buffered =================
// C[m][n] = sum_k A[m][k]*B[n][k]; A,B fp16 2-term splits, K-major.
// Products {00,01,10} -> ~2^-22 relative accuracy. 128x128 tile, 8 warps (32x64),
// K-chunk 32, SMEM row stride 40, 2 stages, 2 blocks/SM.
// SPL: 0 none | 2 also write 2-term fp16 splits of output.
// EPI: 0 C=v | 1 C+=v | 2 C=2v-D | 3 C=exp(2v-D[m]-D[n]) SYMMETRIC + fused rowsum
//      4 C=v+b1[n] | 5 C=relu(v+b1[n]+b2[n]) | 6 C=relu(C+v+b1[n]+b2[n])
//      7 atomic C+=v (split-K over gridDim.x) | 8 atomic C+=2v-D (D only by ks=0)
// EPI3: S0 is reinterpreted as float* rowsum accumulator (pre-zeroed), stride NN per batch.
#define MM_SMEM 81920    // 2 stages * 4 tiles * 5120 * 2B

template<int EPI, int SPL>
__global__ void __launch_bounds__(256, 2)
mma_gemm_k(const hf* __restrict__ A0, const hf* __restrict__ A1,
           const hf* __restrict__ B0, const hf* __restrict__ B1,
           float* __restrict__ C, const float* __restrict__ D,
           const float* __restrict__ bias1, const float* __restrict__ bias2,
           hf* __restrict__ S0, hf* __restrict__ S1,
           int N, int K, int ldC, int ldD,
           long long sA, long long sB, long long sC, long long sD)
{
    constexpr int STAGE_E = 4*5120;
    constexpr bool KSP = (EPI >= 7);

    if (EPI == 3 && blockIdx.x < blockIdx.y) return;

    extern __shared__ __align__(16) hf sm[];
    const int tid = threadIdx.x;
    const int lane = tid & 31, warp = tid >> 5;
    const int wm = warp >> 1, wn = warp & 1;
    const int bz = blockIdx.z;
    const int row0 = blockIdx.y * 128;
    const int col0 = KSP ? 0 : blockIdx.x * 128;
    const int Keff = KSP ? (K / (int)gridDim.x) : K;
    const int kbase = KSP ? (int)blockIdx.x * Keff : 0;

    const hf* src[4] = { A0 + bz*sA + (long long)row0*K + kbase,
                         A1 + bz*sA + (long long)row0*K + kbase,
                         B0 + bz*sB + (long long)col0*K + kbase,
                         B1 + bz*sB + (long long)col0*K + kbase };

    float acc[2][8][4];
#pragma unroll
    for (int i=0;i<2;i++)
#pragma unroll
        for (int j=0;j<8;j++)
#pragma unroll
            for (int u=0;u<4;u++) acc[i][j][u] = 0.f;

    const uint32_t smb = smem_u32(sm);
    const int lrow = lane & 15;
    const int lcol = (lane >> 4) * 8;
    const int r_ld = tid >> 2, q_ld = (tid & 3) * 8;

    auto load_stage = [&](int k0, int st) {
        uint32_t dbase = smb + (uint32_t)st * (STAGE_E*2);
#pragma unroll
        for (int arr = 0; arr < 4; ++arr) {
            const hf* g = src[arr] + k0;
#pragma unroll
            for (int i = 0; i < 2; ++i) {
                int r = r_ld + i*64;
                cpasync16(dbase + (uint32_t)(arr*5120 + r*40 + q_ld)*2,
                          g + (long long)r*K + q_ld);
            }
        }
    };

    const int nk = Keff >> 5;
    load_stage(0, 0);
    CP_COMMIT();

    for (int it = 0; it < nk; ++it) {
        if (it + 1 < nk) { load_stage((it+1)*32, (it+1)&1); CP_COMMIT(); }
        if (it + 1 < nk) CP_WAIT1(); else CP_WAIT0();
        __syncthreads();

        const uint32_t sb = smb + (uint32_t)(it & 1) * (STAGE_E*2);
#pragma unroll
        for (int ks = 0; ks < 2; ++ks) {
            uint32_t af[2][2][4];
#pragma unroll
            for (int s = 0; s < 2; ++s)
#pragma unroll
                for (int mt = 0; mt < 2; ++mt) {
                    int rr = wm*32 + mt*16 + lrow;
                    ldmx4(af[s][mt], sb + (uint32_t)(s*5120 + rr*40 + ks*16 + lcol)*2);
                }
            uint32_t bfr[2][4][4];
#pragma unroll
            for (int s = 0; s < 2; ++s)
#pragma unroll
                for (int np = 0; np < 4; ++np) {
                    int rr = wn*64 + np*16 + lrow;
                    ldmx4(bfr[s][np], sb + (uint32_t)((2+s)*5120 + rr*40 + ks*16 + lcol)*2);
                }
            const int PA[3] = {0,0,1};
            const int PB[3] = {0,1,0};
#pragma unroll
            for (int p = 0; p < 3; ++p) {
#pragma unroll
                for (int np = 0; np < 4; ++np) {
#pragma unroll
                    for (int mt = 0; mt < 2; ++mt) {
                        mma16816(acc[mt][2*np],   af[PA[p]][mt], bfr[PB[p]][np][0], bfr[PB[p]][np][2]);
                        mma16816(acc[mt][2*np+1], af[PA[p]][mt], bfr[PB[p]][np][1], bfr[PB[p]][np][3]);
                    }
                }
            }
        }
        __syncthreads();
    }

    // ---- epilogue ----
    float* Cb = C + bz*sC;
    const float* Db = D ? D + bz*sD : (const float*)0;

    if (EPI == 3) {
        float* tile = (float*)sm;  // 128 x 129 fp32 = 66048 B <= 81920
#pragma unroll
        for (int mt = 0; mt < 2; ++mt)
#pragma unroll
        for (int h = 0; h < 2; ++h) {
            int lm = wm*32 + mt*16 + (lane >> 2) + h*8;
            int gm = row0 + lm;
#pragma unroll
            for (int nt = 0; nt < 8; ++nt) {
                int ln = wn*64 + nt*8 + (lane & 3)*2;
                int gn = col0 + ln;
                float dm = Db[gm];
                float o0 = expf(2.f*acc[mt][nt][h*2]   - dm - Db[gn]);
                float o1 = expf(2.f*acc[mt][nt][h*2+1] - dm - Db[gn+1]);
                *(float2*)(Cb + (long long)gm*ldC + gn) = make_float2(o0, o1);
                tile[lm*129 + ln]   = o0;
                tile[lm*129 + ln+1] = o1;
            }
        }
        __syncthreads();
        const bool offdiag = (blockIdx.x > blockIdx.y);
        if (offdiag) {
            for (int q = tid; q < 128*128; q += 256) {
                int i = q >> 7, j = q & 127;
                Cb[(long long)(col0 + i)*ldC + row0 + j] = tile[j*129 + i];
            }
        }
        float* dvp = (float*)S0 + (long long)bz*NN;
        if (tid < 128) {
            float s = 0.f;
            const float* tr = tile + tid*129;
#pragma unroll 8
            for (int j = 0; j < 128; ++j) s += tr[j];
            atomicAdd(dvp + row0 + tid, s);
        } else if (offdiag) {
            int t = tid - 128;
            float s = 0.f;
#pragma unroll 8
            for (int j = 0; j < 128; ++j) s += tile[j*129 + t];
            atomicAdd(dvp + col0 + t, s);
        }
        return;
    }

    hf *Sb0 = 0, *Sb1 = 0;
    if (SPL) { Sb0 = S0 + bz*sC; Sb1 = S1 + bz*sC; }

#pragma unroll
    for (int mt = 0; mt < 2; ++mt)
#pragma unroll
    for (int h = 0; h < 2; ++h) {
        int gm = row0 + wm*32 + mt*16 + (lane >> 2) + h*8;
#pragma unroll
        for (int nt = 0; nt < 8; ++nt) {
            int gn = col0 + wn*64 + nt*8 + (lane & 3)*2;
            float v0 = acc[mt][nt][h*2], v1 = acc[mt][nt][h*2+1];
            long long off = (long long)gm*ldC + gn;
            float* cp = Cb + off;
            if (EPI == 7) {
                atomicAdd(cp,   v0);
                atomicAdd(cp+1, v1);
                continue;
            }
            if (EPI == 8) {
                float d0 = 0.f, d1 = 0.f;
                if (blockIdx.x == 0) {
                    const float2 dd = *(const float2*)(Db + (long long)gm*ldD + gn);
                    d0 = dd.x; d1 = dd.y;
                }
                atomicAdd(cp,   2.f*v0 - d0);
                atomicAdd(cp+1, 2.f*v1 - d1);
                continue;
            }
            float2 o;
            if (EPI == 0)      { o = make_float2(v0, v1); }
            else if (EPI == 1) { float2 c = *(const float2*)cp; o = make_float2(c.x+v0, c.y+v1); }
            else if (EPI == 2) {
                const float2 dd = *(const float2*)(Db + (long long)gm*ldD + gn);
                o = make_float2(2.f*v0 - dd.x, 2.f*v1 - dd.y);
            }
            else if (EPI == 4) { o = make_float2(v0 + bias1[gn], v1 + bias1[gn+1]); }
            else if (EPI == 5) {
                o = make_float2(fmaxf(v0 + bias1[gn]   + bias2[gn],   0.f),
                                fmaxf(v1 + bias1[gn+1] + bias2[gn+1], 0.f));
            }
            else { // 6
                float2 c = *(const float2*)cp;
                o = make_float2(fmaxf(c.x + v0 + bias1[gn]   + bias2[gn],   0.f),
                                fmaxf(c.y + v1 + bias1[gn+1] + bias2[gn+1], 0.f));
            }
            *(float2*)cp = o;
            if (SPL) {
                unsigned short a0,a1,b0,b1;
                hsplit(o.x,a0,a1); hsplit(o.y,b0,b1);
                *(uint32_t*)(Sb0 + off) = (uint32_t)a0 | ((uint32_t)b0<<16);
                *(uint32_t*)(Sb1 + off) = (uint32_t)a1 | ((uint32_t)b1<<16);
            }
        }
    }
}

// ================= fused elementwise + split kernels =================
__global__ void relu_br_split_k(const float* __restrict__ src, float* __restrict__ dst,
                                const float* __restrict__ br,
                                hf* __restrict__ o0, hf* __restrict__ o1,
                                int total4, int F)
{
    int i = blockIdx.x*blockDim.x + threadIdx.x;
    if (i >= total4) return;
    int f = (i*4) % F;
    float4 v = ((const float4*)src)[i];
    v.x = fmaxf(v.x + br[f],   0.f);
    v.y = fmaxf(v.y + br[f+1], 0.f);
    v.z = fmaxf(v.z + br[f+2], 0.f);
    v.w = fmaxf(v.w + br[f+3], 0.f);
    ((float4*)dst)[i] = v;
    unsigned short a0,a1,b0,b1,c0,c1,d0,d1;
    hsplit(v.x,a0,a1); hsplit(v.y,b0,b1); hsplit(v.z,c0,c1); hsplit(v.w,d0,d1);
    ((uint2*)o0)[i] = make_uint2((uint32_t)a0 | ((uint32_t)b0<<16), (uint32_t)c0 | ((uint32_t)d0<<16));
    ((uint2*)o1)[i] = make_uint2((uint32_t)a1 | ((uint32_t)b1<<16), (uint32_t)c1 | ((uint32_t)d1<<16));
}

// split a 128-col slice of Tb [rows, ld 512] into RS slot (same offsets)
__global__ void rs_slice_split_k(const float* __restrict__ src,
                                 hf* __restrict__ o0, hf* __restrict__ o1,
                                 int colOff)
{
    int i = blockIdx.x*blockDim.x + threadIdx.x;          // over rows*32
    if (i >= BB*NN*32) return;
    int row = i >> 5, c4 = (i & 31) * 4;
    long long off = (long long)row*512 + colOff + c4;
    float4 v = *(const float4*)(src + off);
    unsigned short a0,a1,b0,b1,c0,c1,d0,d1;
    hsplit(v.x,a0,a1); hsplit(v.y,b0,b1); hsplit(v.z,c0,c1); hsplit(v.w,d0,d1);
    *(uint2*)(o0 + off) = make_uint2((uint32_t)a0 | ((uint32_t)b0<<16), (uint32_t)c0 | ((uint32_t)d0<<16));
    *(uint2*)(o1 + off) = make_uint2((uint32_t)a1 | ((uint32_t)b1<<16), (uint32_t)c1 | ((uint32_t)d1<<16));
}

// transpose + split
__global__ void tr_split_k(const float* __restrict__ in,
                           hf* __restrict__ o0, hf* __restrict__ o1,
                           int inLd, int outLd, long long inS, long long outS)
{
    __shared__ float t[32][33];
    int r0 = blockIdx.x*32, c0 = blockIdx.y*32;
    const float* ip = in + (long long)blockIdx.z*inS;
    for (int i = threadIdx.y; i < 32; i += 8)
        t[i][threadIdx.x] = ip[(long long)(r0+i)*inLd + c0 + threadIdx.x];
    __syncthreads();
    long long ob = (long long)blockIdx.z*outS;
    for (int i = threadIdx.y; i < 32; i += 8) {
        float x = t[threadIdx.x][i];
        unsigned short s0,s1;
        hsplit(x,s0,s1);
        long long o = ob + (long long)(c0+i)*outLd + r0 + threadIdx.x;
        o0[o] = __ushort_as_half(s0);
        o1[o] = __ushort_as_half(s1);
    }
}

// fused Laplacian normalize + split (2 terms)
__global__ void adjnorm_split_k(const float* __restrict__ adj, const float* __restrict__ dinv,
                                hf* __restrict__ o0, hf* __restrict__ o1)
{
    long long i4 = (long long)blockIdx.x*blockDim.x + threadIdx.x;
    long long tot4 = (long long)BB*NN*NN/4;
    if (i4 >= tot4) return;
    long long bse = i4*4;
    int c = (int)(bse % NN);
    long long row = bse / NN;
    int r = (int)(row % NN);
    float dr = dinv[row];
    const float* dc = dinv + (row - r);
    float4 v = ((const float4*)adj)[i4];
    float w[4];
    w[0] = v.x*dr*dc[c];   w[1] = v.y*dr*dc[c+1];
    w[2] = v.z*dr*dc[c+2]; w[3] = v.w*dr*dc[c+3];
#pragma unroll
    for (int u=0;u<4;u++) w[u] = (r == c+u) ? (1.f - w[u]) : (-w[u]);
    unsigned short a0,a1,b0,b1,c0s,c1s,d0,d1;
    hsplit(w[0],a0,a1); hsplit(w[1],b0,b1); hsplit(w[2],c0s,c1s); hsplit(w[3],d0,d1);
    ((uint2*)o0)[i4] = make_uint2((uint32_t)a0 | ((uint32_t)b0<<16), (uint32_t)c0s | ((uint32_t)d0<<16));
    ((uint2*)o1)[i4] = make_uint2((uint32_t)a1 | ((uint32_t)b1<<16), (uint32_t)c1s | ((uint32_t)d1<<16));
}

__global__ void zero_k(float* __restrict__ p, int n)
{
    int i = blockIdx.x*blockDim.x + threadIdx.x;
    if (i < n) p[i] = 0.f;
}
__global__ void rsqrt_k(float* __restrict__ p, int n)
{
    int i = blockIdx.x*blockDim.x + threadIdx.x;
    if (i < n) p[i] = rsqrtf(p[i]);
}
__global__ void zero_h_k(hf* __restrict__ p, long long n4)
{
    long long i = (long long)blockIdx.x*blockDim.x + threadIdx.x;
    if (i < n4) ((uint2*)p)[i] = make_uint2(0u, 0u);
}

// pad x [rows,6] -> splits [rows,32] (cols 6..31 zero)
__global__ void xpad_split_k(const float* __restrict__ x, hf* __restrict__ o0, hf* __restrict__ o1)
{
    int row = blockIdx.x*blockDim.x + threadIdx.x;
    if (row >= BB*NN) return;
    const float* xr = x + (long long)row*6;
    hf* p0 = o0 + (long long)row*32;
    hf* p1 = o1 + (long long)row*32;
#pragma unroll
    for (int c = 0; c < 6; ++c) {
        unsigned short s0,s1;
        hsplit(xr[c], s0, s1);
        p0[c] = __ushort_as_half(s0);
        p1[c] = __ushort_as_half(s1);
    }
#pragma unroll
    for (int c = 6; c < 32; ++c) { p0[c] = __ushort_as_half(0); p1[c] = __ushort_as_half(0); }
}

// W0 [6][22][128] -> padded splits [128 rows, 192 K]
__global__ void w0pad_split_k(const float* __restrict__ W, hf* __restrict__ o0, hf* __restrict__ o1)
{
    int idx = blockIdx.x*blockDim.x + threadIdx.x;
    if (idx >= 128*192) return;
    int n = idx / 192, kc = idx % 192;
    int k = kc >> 5, c = kc & 31;
    float v = (c < 22) ? W[((long long)k*22 + c)*128 + n] : 0.f;
    unsigned short s0,s1;
    hsplit(v, s0, s1);
    o0[idx] = __ushort_as_half(s0);
    o1[idx] = __ushort_as_half(s1);
}

// ================= narrow L@T (cin=22) symmetric split-K =================
__global__ void __launch_bounds__(256)
lx_part_k(const float* __restrict__ L, const float* __restrict__ T, float* __restrict__ part)
{
    const int b = blockIdx.z;
    const int s = blockIdx.y;
    const int r0 = blockIdx.x * 512 + threadIdx.x * 2;
    const float* Lb = L + (long long)b*NN*NN;
    const float* Tp = T + (long long)b*NN*22;
    __shared__ float Tsh[32][24];
    unsigned long long accA[11], accB[11];
#pragma unroll
    for (int j=0;j<11;j++){ accA[j]=0ull; accB[j]=0ull; }
    const int kbeg = s * (NN/NSPLIT);
    const int kend = kbeg + (NN/NSPLIT);
    for (int k0 = kbeg; k0 < kend; k0 += 32) {
        for (int idx = threadIdx.x; idx < 32*22; idx += 256) {
            int kk = idx / 22, c = idx % 22;
            Tsh[kk][c] = Tp[(long long)(k0+kk)*22 + c];
        }
        __syncthreads();
#pragma unroll
        for (int kk = 0; kk < 32; ++kk) {
            float2 l2 = *(const float2*)(Lb + (long long)(k0+kk)*NN + r0);
            unsigned long long lx = pk2(l2.x), ly = pk2(l2.y);
#pragma unroll
            for (int j=0;j<11;j++) {
                unsigned long long tp = *(const unsigned long long*)&Tsh[kk][2*j];
                fma2(accA[j], lx, tp);
                fma2(accB[j], ly, tp);
            }
        }
        __syncthreads();
    }
    float* p = part + ((long long)(s*BB + b)*NN)*24;
#pragma unroll
    for (int j=0;j<11;j++) {
        p[(long long)r0*24     + 2*j]   = lo32(accA[j]);
        p[(long long)r0*24     + 2*j+1] = hi32(accA[j]);
        p[(long long)(r0+1)*24 + 2*j]   = lo32(accB[j]);
        p[(long long)(r0+1)*24 + 2*j+1] = hi32(accB[j]);
    }
}

// reduce + write T fp32 (22-col) + fused fp16 splits into stacked slot (ld 192)
__global__ void lx_reduce_k(const float* __restrict__ part, float* __restrict__ Tout,
                            const float* __restrict__ Tprev, int mode,
                            hf* __restrict__ s0, hf* __restrict__ s1, int slotoff)
{
    int idx = blockIdx.x*blockDim.x + threadIdx.x;
    if (idx >= BB*NN*22) return;
    int c   = idx % 22;
    int row = idx / 22;
    float s = 0.f;
#pragma unroll
    for (int k=0;k<NSPLIT;k++)
        s += part[((long long)k*BB*NN + row)*24 + c];
    float v = (mode == 2) ? (2.f*s - Tprev[(long long)row*22 + c]) : s;
    Tout[(long long)row*22 + c] = v;
    unsigned short a0,a1;
    hsplit(v,a0,a1);
    long long so = (long long)row*192 + slotoff + c;
    s0[so] = __ushort_as_half(a0);
    s1[so] = __ushort_as_half(a1);
}

// ================= elementwise / reductions =================
__global__ void concat_input_k(const float* __restrict__ x, const int* __restrict__ cat,
                               float* __restrict__ X0, hf* __restrict__ s0, hf* __restrict__ s1)
{
    int idx = blockIdx.x*blockDim.x + threadIdx.x;
    if (idx >= BB*NN) return;
    int b = idx / NN;
    float* o = X0 + (long long)idx*22;
    hf* p0 = s0 + (long long)idx*192;
    hf* p1 = s1 + (long long)idx*192;
    const float* xi = x + (long long)idx*6;
    int c = cat[b];
#pragma unroll
    for (int i=0;i<22;i++) {
        float v = (i < 6) ? xi[i] : ((i-6)==c ? 1.f : 0.f);
        o[i] = v;
        unsigned short h0,h1;
        hsplit(v,h0,h1);
        p0[i] = __ushort_as_half(h0);
        p1[i] = __ushort_as_half(h1);
    }
}

__device__ __forceinline__ float block_reduce_sum(float v)
{
    __shared__ float s[32];
    int lane = threadIdx.x & 31, wid = threadIdx.x >> 5;
#pragma unroll
    for (int o=16;o>0;o>>=1) v += __shfl_down_sync(0xffffffffu, v, o);
    if (lane == 0) s[wid] = v;
    __syncthreads();
    int nw = blockDim.x >> 5;
    v = (threadIdx.x < nw) ? s[threadIdx.x] : 0.f;
    if (wid == 0) {
#pragma unroll
        for (int o=16;o>0;o>>=1) v += __shfl_down_sync(0xffffffffu, v, o);
    }
    return v;
}

__global__ void row_sq_k(const float* __restrict__ X, float* __restrict__ sq, int F)
{
    const float* r = X + (long long)blockIdx.x * F;
    float s = 0.f;
    for (int i = threadIdx.x; i < F; i += blockDim.x) { float v = r[i]; s += v*v; }
    s = block_reduce_sum(s);
    if (threadIdx.x == 0) sq[blockIdx.x] = s;
}

__global__ void row_sq_v4_k(const float* __restrict__ X, float* __restrict__ sq, int F4)
{
    const float4* r = (const float4*)X + (long long)blockIdx.x * F4;
    float s = 0.f;
    for (int i = threadIdx.x; i < F4; i += blockDim.x) {
        float4 v = r[i];
        s += v.x*v.x + v.y*v.y + v.z*v.z + v.w*v.w;
    }
    s = block_reduce_sum(s);
    if (threadIdx.x == 0) sq[blockIdx.x] = s;
}

__global__ void normalize_v4_k(float* __restrict__ L, const float* __restrict__ dinv)
{
    long long i4 = (long long)blockIdx.x*blockDim.x + threadIdx.x;
    long long tot4 = (long long)BB*NN*NN/4;
    if (i4 >= tot4) return;
    long long base = i4*4;
    int c = (int)(base % NN);
    long long row = base / NN;
    int r = (int)(row % NN);
    float dr = dinv[row];
    const float* dc = dinv + (row - r);
    float4 v = ((const float4*)L)[i4];
    v.x *= dr*dc[c];   v.y *= dr*dc[c+1];
    v.z *= dr*dc[c+2]; v.w *= dr*dc[c+3];
    float4 o;
    o.x = (r==c  ) ? 1.f-v.x : -v.x;
    o.y = (r==c+1) ? 1.f-v.y : -v.y;
    o.z = (r==c+2) ? 1.f-v.z : -v.z;
    o.w = (r==c+3) ? 1.f-v.w : -v.w;
    ((float4*)L)[i4] = o;
}

__global__ void relu_2b_k(float* __restrict__ p, const float* __restrict__ b1,
                          const float* __restrict__ b2, int total, int F)
{
    int i = blockIdx.x*blockDim.x + threadIdx.x;
    if (i < total) { int f = i % F; p[i] = fmaxf(p[i] + b1[f] + b2[f], 0.f); }
}

// ================= legacy fp32 tiled SGEMM (FC2 only) =================
template<int BM,int BN,int BK,int TM,int TN,int MODE,bool TB>
__global__ void __launch_bounds__((BM/TM)*(BN/TN))
gemm_k(const float* __restrict__ A, const float* __restrict__ Bm,
       float* C, const float* D,
       int M, int N, int K,
       long long sA, long long sB, long long sC, long long sD)
{
    constexpr int NT = (BM/TM)*(BN/TN);
    const int bz = blockIdx.z;
    A  += (long long)bz * sA;
    Bm += (long long)bz * sB;
    C  += (long long)bz * sC;
    if (D) D += (long long)bz * sD;
    const int row0 = blockIdx.y * BM;
    const int col0 = blockIdx.x * BN;
    __shared__ float As[BK][BM+4];
    __shared__ float Bs[BK][BN+4];
    const int tid = threadIdx.x;
    const int tx  = tid % (BN/TN);
    const int ty  = tid / (BN/TN);
    float acc[TM][TN];
#pragma unroll
    for (int i=0;i<TM;i++)
#pragma unroll
        for (int j=0;j<TN;j++) acc[i][j] = 0.f;
    for (int k0 = 0; k0 < K; k0 += BK) {
#pragma unroll
        for (int idx = tid; idx < BM*BK; idx += NT) {
            int m  = idx / BK, kk = idx % BK;
            int gm = row0 + m, gk = k0 + kk;
            As[kk][m] = (gm < M && gk < K) ? A[(long long)gm*K + gk] : 0.f;
        }
        if (TB) {
#pragma unroll
            for (int idx = tid; idx < BK*BN; idx += NT) {
                int n  = idx / BK, kk = idx % BK;
                int gn = col0 + n, gk = k0 + kk;
                Bs[kk][n] = (gn < N && gk < K) ? Bm[(long long)gn*K + gk] : 0.f;
            }
        } else {
#pragma unroll
            for (int idx = tid; idx < BK*BN; idx += NT) {
                int kk = idx / BN, n = idx % BN;
                int gk = k0 + kk, gn = col0 + n;
                Bs[kk][n] = (gk < K && gn < N) ? Bm[(long long)gk*N + gn] : 0.f;
            }
        }
        __syncthreads();
#pragma unroll
        for (int kk = 0; kk < BK; ++kk) {
            float a[TM], b[TN];
#pragma unroll
            for (int i=0;i<TM;++i) a[i] = As[kk][ty*TM + i];
#pragma unroll
            for (int j=0;j<TN;++j) b[j] = Bs[kk][tx*TN + j];
#pragma unroll
            for (int i=0;i<TM;++i)
#pragma unroll
                for (int j=0;j<TN;++j)
                    acc[i][j] = fmaf(a[i], b[j], acc[i][j]);
        }
        __syncthreads();
    }
#pragma unroll
    for (int i=0;i<TM;++i) {
        int gm = row0 + ty*TM + i;
        if (gm >= M) continue;
#pragma unroll
        for (int j=0;j<TN;++j) {
            int gn = col0 + tx*TN + j;
            if (gn >= N) continue;
            long long off = (long long)gm*N + gn;
            float v = acc[i][j];
            if (MODE == 0)      C[off] = v;
            else if (MODE == 1) C[off] += v;
            else                C[off] = expf(2.f*v - D[gm] - D[gn]);
        }
    }
}

// ================= host helpers =================
static inline void gemm_big(int mode, const float* A, const float* B, float* C, const float* D,
                            int M, int N, int K, int batch,
                            long long sA, long long sB, long long sC, long long sD)
{
    dim3 g((N+63)/64, (M+127)/128, batch);
    switch (mode) {
      case 0: gemm_k<128,64,16,8,4,0,false><<<g,256>>>(A,B,C,D,M,N,K,sA,sB,sC,sD); break;
      case 1: gemm_k<128,64,16,8,4,1,false><<<g,256>>>(A,B,C,D,M,N,K,sA,sB,sC,sD); break;
    }
}

static inline void tc_gemm(int epi, int spl, hf* const* As, hf* const* Bs,
                           float* C, const float* D, const float* b1, const float* b2,
                           hf* s0, hf* s1,
                           int Mb, int N, int K, int ldC, int ldD, int batch,
                           long long sA, long long sB, long long sC, long long sD)
{
    dim3 g(N/128, Mb/128, batch);
    dim3 g2(2, Mb/128, batch);   // split-K grids (EPI 7/8)
    switch (epi*10 + spl) {
      case 0:  mma_gemm_k<0,0><<<g,256,MM_SMEM>>>(As[0],As[1],Bs[0],Bs[1],C,D,b1,b2,s0,s1,N,K,ldC,ldD,sA,sB,sC,sD); break;
      case 2:  mma_gemm_k<0,2><<<g,256,MM_SMEM>>>(As[0],As[1],Bs[0],Bs[1],C,D,b1,b2,s0,s1,N,K,ldC,ldD,sA,sB,sC,sD); break;
      case 10: mma_gemm_k<1,0><<<g,256,MM_SMEM>>>(As[0],As[1],Bs[0],Bs[1],C,D,b1,b2,s0,s1,N,K,ldC,ldD,sA,sB,sC,sD); break;
      case 12: mma_gemm_k<1,2><<<g,256,MM_SMEM>>>(As[0],As[1],Bs[0],Bs[1],C,D,b1,b2,s0,s1,N,K,ldC,ldD,sA,sB,sC,sD); break;
      case 22: mma_gemm_k<2,2><<<g,256,MM_SMEM>>>(As[0],As[1],Bs[0],Bs[1],C,D,b1,b2,s0,s1,N,K,ldC,ldD,sA,sB,sC,sD); break;
      case 30: mma_gemm_k<3,0><<<g,256,MM_SMEM>>>(As[0],As[1],Bs[0],Bs[1],C,D,b1,b2,s0,s1,N,K,ldC,ldD,sA,sB,sC,sD); break;
      case 40: mma_gemm_k<4,0><<<g,256,MM_SMEM>>>(As[0],As[1],Bs[0],Bs[1],C,D,b1,b2,s0,s1,N,K,ldC,ldD,sA,sB,sC,sD); break;
      case 42: mma_gemm_k<4,2><<<g,256,MM_SMEM>>>(As[0],As[1],Bs[0],Bs[1],C,D,b1,b2,s0,s1,N,K,ldC,ldD,sA,sB,sC,sD); break;
      case 52: mma_gemm_k<5,2><<<g,256,MM_SMEM>>>(As[0],As[1],Bs[0],Bs[1],C,D,b1,b2,s0,s1,N,K,ldC,ldD,sA,sB,sC,sD); break;
      case 70: mma_gemm_k<7,0><<<g2,256,MM_SMEM>>>(As[0],As[1],Bs[0],Bs[1],C,D,b1,b2,s0,s1,N,K,ldC,ldD,sA,sB,sC,sD); break;
      case 80: mma_gemm_k<8,0><<<g2,256,MM_SMEM>>>(As[0],As[1],Bs[0],Bs[1],C,D,b1,b2,s0,s1,N,K,ldC,ldD,sA,sB,sC,sD); break;
    }
}

extern "C" void kernel_launch(void* const* d_in, const int* in_sizes, int n_in,
                              void* d_out, int out_size)
{
    (void)in_sizes; (void)n_in; (void)out_size;

    cudaFuncSetAttribute(mma_gemm_k<0,0>, cudaFuncAttributeMaxDynamicSharedMemorySize, MM_SMEM);
    cudaFuncSetAttribute(mma_gemm_k<0,2>, cudaFuncAttributeMaxDynamicSharedMemorySize, MM_SMEM);
    cudaFuncSetAttribute(mma_gemm_k<1,0>, cudaFuncAttributeMaxDynamicSharedMemorySize, MM_SMEM);
    cudaFuncSetAttribute(mma_gemm_k<1,2>, cudaFuncAttributeMaxDynamicSharedMemorySize, MM_SMEM);
    cudaFuncSetAttribute(mma_gemm_k<2,2>, cudaFuncAttributeMaxDynamicSharedMemorySize, MM_SMEM);
    cudaFuncSetAttribute(mma_gemm_k<3,0>, cudaFuncAttributeMaxDynamicSharedMemorySize, MM_SMEM);
    cudaFuncSetAttribute(mma_gemm_k<4,0>, cudaFuncAttributeMaxDynamicSharedMemorySize, MM_SMEM);
    cudaFuncSetAttribute(mma_gemm_k<4,2>, cudaFuncAttributeMaxDynamicSharedMemorySize, MM_SMEM);
    cudaFuncSetAttribute(mma_gemm_k<5,2>, cudaFuncAttributeMaxDynamicSharedMemorySize, MM_SMEM);
    cudaFuncSetAttribute(mma_gemm_k<7,0>, cudaFuncAttributeMaxDynamicSharedMemorySize, MM_SMEM);
    cudaFuncSetAttribute(mma_gemm_k<8,0>, cudaFuncAttributeMaxDynamicSharedMemorySize, MM_SMEM);

    const float* x   = (const float*)d_in[0];
    const int*   cat = (const int*)  d_in[1];
    const float* Wc[3] = {(const float*)d_in[2], (const float*)d_in[4], (const float*)d_in[6]};
    const float* bc[3] = {(const float*)d_in[3], (const float*)d_in[5], (const float*)d_in[7]};
    const float* fw[3] = {(const float*)d_in[8], (const float*)d_in[10], (const float*)d_in[12]};
    const float* fb[3] = {(const float*)d_in[9], (const float*)d_in[11], (const float*)d_in[13]};
    const float* br[6];
    for (int i=0;i<6;i++) br[i] = (const float*)d_in[14+i];
    float* out = (float*)d_out;

    float *L,*sqv,*dv,*X0,*Ta,*Tb,*pre,*act0,*skip,*act2,*fc0,*fc1,*part;
    cudaGetSymbolAddress((void**)&L,   g_L);
    cudaGetSymbolAddress((void**)&sqv, g_sq);
    cudaGetSymbolAddress((void**)&dv,  g_dinv);
    cudaGetSymbolAddress((void**)&X0,  g_X0);
    cudaGetSymbolAddress((void**)&Ta,  g_Ta);
    cudaGetSymbolAddress((void**)&Tb,  g_Tb);
    cudaGetSymbolAddress((void**)&pre, g_pre);
    cudaGetSymbolAddress((void**)&act0,g_act0);
    cudaGetSymbolAddress((void**)&skip,g_skip);
    cudaGetSymbolAddress((void**)&act2,g_act2);
    cudaGetSymbolAddress((void**)&fc0, g_fc0);
    cudaGetSymbolAddress((void**)&fc1, g_fc1);
    cudaGetSymbolAddress((void**)&part,g_part);

    hf *LS[2], *RS[2], *TS[2], *SK[2], *WT[2];
    cudaGetSymbolAddress((void**)&LS[0], g_LS0); cudaGetSymbolAddress((void**)&LS[1], g_LS1);
    cudaGetSymbolAddress((void**)&RS[0], g_RS0); cudaGetSymbolAddress((void**)&RS[1], g_RS1);
    cudaGetSymbolAddress((void**)&TS[0], g_TS0); cudaGetSymbolAddress((void**)&TS[1], g_TS1);
    cudaGetSymbolAddress((void**)&SK[0], g_SK0); cudaGetSymbolAddress((void**)&SK[1], g_SK1);
    cudaGetSymbolAddress((void**)&WT[0], g_WT0); cudaGetSymbolAddress((void**)&WT[1], g_WT1);

    const long long sL = (long long)NN*NN;
    const long long tot4 = (long long)BB*NN*NN/4;
    const long long preoff = (long long)BB*NN*512;   // pre-splits region inside RS

    // weight layout in WT (transposed [out,in], K-major)
    const long long oW1a = 0;
    const long long oW1s = oW1a + 512LL*128;
    const long long oW2a = oW1s + 512LL*512;
    const long long oW2s = oW2a + 1024LL*512;
    const long long oF0  = oW2s + 1024LL*1024;
    const long long oF1a = oF0  + 512LL*1024;
    const long long oF1b = oF1a + 128LL*512;
    const long long oW0  = oF1b + 128LL*512;         // W0 padded [128, 192]

    {   dim3 g(128/32, 512/32, 1);
        tr_split_k<<<g,dim3(32,8)>>>(Wc[1], WT[0]+oW1a, WT[1]+oW1a, 512, 128, 0, 0); }
    {   dim3 g(128/32, 512/32, 4);
        tr_split_k<<<g,dim3(32,8)>>>(Wc[1]+128LL*512, WT[0]+oW1s, WT[1]+oW1s,
                                     512, 512, 128LL*512, 128); }
    {   dim3 g(512/32, 1024/32, 1);
        tr_split_k<<<g,dim3(32,8)>>>(Wc[2], WT[0]+oW2a, WT[1]+oW2a, 1024, 512, 0, 0); }
    {   dim3 g(512/32, 1024/32, 2);
        tr_split_k<<<g,dim3(32,8)>>>(Wc[2]+512LL*1024, WT[0]+oW2s, WT[1]+oW2s,
                                     1024, 1024, 512LL*1024, 512); }
    {   dim3 g(1024/32, 512/32, 1);
        tr_split_k<<<g,dim3(32,8)>>>(fw[0], WT[0]+oF0, WT[1]+oF0, 512, 1024, 0, 0); }
    {   dim3 g(512/32, 128/32, 1);
        tr_split_k<<<g,dim3(32,8)>>>(fw[1],           WT[0]+oF1a, WT[1]+oF1a, 128, 512, 0, 0);
        tr_split_k<<<g,dim3(32,8)>>>(fw[1]+512LL*128, WT[0]+oF1b, WT[1]+oF1b, 128, 512, 0, 0); }
    w0pad_split_k<<<(128*192+255)/256,256>>>(Wc[0], WT[0]+oW0, WT[1]+oW0);

    auto wp = [&](long long off){ static hf* tmp[2]; tmp[0]=WT[0]+off; tmp[1]=WT[1]+off; return (hf* const*)tmp; };

    auto laplacian_tc = [&](const float* feat, int F, hf* f0, hf* f1) {
        row_sq_v4_k<<<BB*NN,128>>>(feat, sqv, F/4);
        zero_k<<<(BB*NN+255)/256,256>>>(dv, BB*NN);
        hf* FS[2] = {f0, f1};
        tc_gemm(3, 0, FS, FS, L, sqv, 0, 0, (hf*)dv, 0, NN, NN, F, NN, 0, BB,
                (long long)NN*F, (long long)NN*F, sL, NN);
        rsqrt_k<<<(BB*NN+255)/256,256>>>(dv, BB*NN);
        adjnorm_split_k<<<(unsigned)((tot4+255)/256),256>>>(L, dv, LS[0], LS[1]);
    };

    auto split_tr = [&](const float* src, int cin, int inLd) {
        dim3 g(NN/32, cin/32, BB);
        tr_split_k<<<g,dim3(32,8)>>>(src, TS[0], TS[1], inLd, NN,
                                     (long long)NN*inLd, (long long)cin*NN);
    };

    auto lx22 = [&](int mode, const float* Tin, float* Tout, const float* Tprev, int slot) {
        dim3 g(NN/512, NSPLIT, BB);
        lx_part_k<<<g,256>>>(L, Tin, part);
        lx_reduce_k<<<(BB*NN*22+255)/256,256>>>(part, Tout, Tprev, mode, RS[0], RS[1], slot*32);
    };

    // ---- input assembly + stacked-T0 splits; F=6 Laplacian via tensor path ----
    zero_h_k<<<(unsigned)(((long long)BB*NN*192/4+255)/256),256>>>(RS[0], (long long)BB*NN*192/4);
    zero_h_k<<<(unsigned)(((long long)BB*NN*192/4+255)/256),256>>>(RS[1], (long long)BB*NN*192/4);
    concat_input_k<<<(BB*NN+127)/128,128>>>(x, cat, X0, RS[0], RS[1]);
    xpad_split_k<<<(BB*NN+127)/128,128>>>(x, SK[0], SK[1]);
    {
        row_sq_k<<<BB*NN,64>>>(x, sqv, 6);
        zero_k<<<(BB*NN+255)/256,256>>>(dv, BB*NN);
        tc_gemm(3, 0, SK, SK, L, sqv, 0, 0, (hf*)dv, 0, NN, NN, 32, NN, 0, BB,
                (long long)NN*32, (long long)NN*32, sL, NN);
        rsqrt_k<<<(BB*NN+255)/256,256>>>(dv, BB*NN);
        normalize_v4_k<<<(unsigned)((tot4+255)/256),256>>>(L, dv);   // fp32 L for lx22
    }

    // ---- conv 0: cheb recursion (fp32) with fused stacked splits; ONE T@W GEMM K=192 ----
    {
        lx22(0, X0, Ta, nullptr, 1);
        const float* Tprev = X0; float* Tcur = Ta;
        for (int k = 2; k < 6; ++k) {
            float* Tnext = (Tprev == X0) ? Tb : (float*)Tprev;
            lx22(2, Tcur, Tnext, Tprev, k);
            Tprev = Tcur; Tcur = Tnext;
        }
        tc_gemm(4, 2, RS, wp(oW0), pre, 0, bc[0], 0, RS[0]+preoff, RS[1]+preoff,
                BB*NN, 128, 192, 128, 0, 1, 0,0,0,0);
    }

    // ---- Laplacian #2 (F=128) ----
    laplacian_tc(pre, 128, RS[0]+preoff, RS[1]+preoff);
    relu_br_split_k<<<(BB*NN*128/4+255)/256,256>>>(pre, act0, br[0], SK[0], SK[1], BB*NN*128/4, 128);

    // ---- conv 1: cin=128 -> 512, K=5; split-K L@T into zeroed Tb, slice-splits to RS ----
    {
        const int cin = 128;
        const long long sTall = (long long)NN*512;
        split_tr(act0, cin, cin);
        tc_gemm(4, 0, SK, wp(oW1a), pre, 0, bc[1], 0, 0,0, BB*NN, 512, cin, 512, 0, 1, 0,0,0,0);
        zero_k<<<(BB*NN*512+255)/256,256>>>(Tb, BB*NN*512);
        // T1 (atomic C+=v)
        tc_gemm(7, 0, LS, TS, Tb, 0, 0, 0, 0,0, NN, cin, NN, 512, 0, BB, sL, (long long)cin*NN, sTall, 0);
        rs_slice_split_k<<<(BB*NN*32+255)/256,256>>>(Tb, RS[0], RS[1], 0);
        split_tr(Tb + 0, cin, 512);
        // T2 = 2 L@T1 - act0
        tc_gemm(8, 0, LS, TS, Tb + 128, act0, 0, 0, 0,0, NN, cin, NN, 512, cin, BB, sL, (long long)cin*NN, sTall, (long long)NN*cin);
        rs_slice_split_k<<<(BB*NN*32+255)/256,256>>>(Tb, RS[0], RS[1], 128);
        split_tr(Tb + 128, cin, 512);
        // T3 = 2 L@T2 - T1
        tc_gemm(8, 0, LS, TS, Tb + 256, Tb + 0, 0, 0, 0,0, NN, cin, NN, 512, 512, BB, sL, (long long)cin*NN, sTall, sTall);
        rs_slice_split_k<<<(BB*NN*32+255)/256,256>>>(Tb, RS[0], RS[1], 256);
        split_tr(Tb + 256, cin, 512);
        // T4 = 2 L@T3 - T2
        tc_gemm(8, 0, LS, TS, Tb + 384, Tb + 128, 0, 0, 0,0, NN, cin, NN, 512, 512, BB, sL, (long long)cin*NN, sTall, sTall);
        rs_slice_split_k<<<(BB*NN*32+255)/256,256>>>(Tb, RS[0], RS[1], 384);
        // batched T@W (K=512) -> pre, emit pre splits for Laplacian #3
        tc_gemm(1, 2, RS, wp(oW1s), pre, 0, 0, 0, RS[0]+preoff, RS[1]+preoff,
                BB*NN, 512, 512, 512, 0, 1, 0,0,0,0);
    }

    // ---- Laplacian #3 (F=512) ----
    laplacian_tc(pre, 512, RS[0]+preoff, RS[1]+preoff);
    relu_br_split_k<<<(BB*NN*512/4+255)/256,256>>>(pre, skip, br[1], SK[0], SK[1], BB*NN*512/4, 512);

    // ---- conv 2: cin=512 -> 1024, K=3; T1..T2 stacked in act2 [M,1024] ----
    {
        const int cin = 512;
        const long long sTall = (long long)NN*1024;
        split_tr(skip, cin, cin);
        tc_gemm(4, 0, SK, wp(oW2a), pre, 0, bc[2], 0, 0,0, BB*NN, 1024, cin, 1024, 0, 1, 0,0,0,0);
        tc_gemm(0, 2, LS, TS, act2, 0, 0, 0, RS[0], RS[1], NN, cin, NN, 1024, 0, BB, sL, (long long)cin*NN, sTall, 0);
        split_tr(act2 + 0, cin, 1024);
        tc_gemm(2, 2, LS, TS, act2 + 512, skip, 0, 0, RS[0]+512, RS[1]+512, NN, cin, NN, 1024, cin, BB, sL, (long long)cin*NN, sTall, (long long)NN*cin);
        tc_gemm(1, 0, RS, wp(oW2s), pre, 0, 0, 0, 0,0, BB*NN, 1024, 1024, 1024, 0, 1, 0,0,0,0);
    }
    relu_br_split_k<<<(BB*NN*1024/4+255)/256,256>>>(pre, act2, br[2], RS[0], RS[1], BB*NN*1024/4, 1024);

    // ---- FC0: 1024 -> 512, fused bias+br+relu; emit fc0 splits into TS ----
    tc_gemm(5, 2, RS, wp(oF0), fc0, 0, fb[0], br[3], TS[0], TS[1], BB*NN, 512, 1024, 512, 0, 1, 0,0,0,0);

    // ---- FC1: concat(fc0, skip) -> 128; split-K accumulation + fused relu pass ----
    zero_k<<<(BB*NN*128+255)/256,256>>>(fc1, BB*NN*128);
    tc_gemm(7, 0, TS, wp(oF1a), fc1, 0, 0, 0, 0,0, BB*NN, 128, 512, 128, 0, 1, 0,0,0,0);
    tc_gemm(7, 0, SK, wp(oF1b), fc1, 0, 0, 0, 0,0, BB*NN, 128, 512, 128, 0, 1, 0,0,0,0);
    relu_2b_k<<<(BB*NN*128+255)/256,256>>>(fc1, fb[1], br[4], BB*NN*128, 128);

    // ---- FC2: 128 -> 50 (fp32 path) ----
    gemm_big(0, fc1, fw[2], out, nullptr, BB*NN, 50, 128, 1, 0,0,0,0);
    relu_2b_k<<<(BB*NN*50+255)/256,256>>>(out, fb[2], br[5], BB*NN*50, 50);
}

// round 17
// speedup vs baseline: 1.0122x; 1.0122x over previous
#include <cuda_runtime.h>
#include <cuda_fp16.h>
#include <cstdint>
#include <math.h>

#define BB 8
#define NN 2048
#define NSPLIT 8

typedef __half hf;

// ================= scratch (device globals; allocation-free) =================
__device__ float g_L   [BB*(size_t)NN*NN];
__device__ float g_sq  [BB*NN];
__device__ float g_dinv[BB*NN];
__device__ float g_X0  [BB*NN*22];
__device__ float g_Ta  [BB*NN*512];
__device__ float g_Tb  [BB*NN*512];      // conv1 Tall [M, 512]
__device__ float g_pre [BB*NN*1024];
__device__ float g_act0[BB*NN*128];
__device__ float g_skip[BB*NN*512];
__device__ float g_act2[BB*NN*1024];     // conv2 Tall, then relu output
__device__ float g_fc0 [BB*NN*512];
__device__ float g_fc1 [BB*NN*128];
__device__ float g_part[(size_t)NSPLIT*BB*NN*24];

// fp16 split buffers (2 terms)
__device__ hf g_LS0[BB*(size_t)NN*NN];
__device__ hf g_LS1[BB*(size_t)NN*NN];
__device__ hf g_RS0[BB*(size_t)NN*1024];
__device__ hf g_RS1[BB*(size_t)NN*1024];
__device__ hf g_TS0[BB*(size_t)512*NN];
__device__ hf g_TS1[BB*(size_t)512*NN];
__device__ hf g_SK0[BB*(size_t)NN*512];
__device__ hf g_SK1[BB*(size_t)NN*512];
#define WT_TOTAL 2580480
__device__ hf g_WT0[WT_TOTAL];
__device__ hf g_WT1[WT_TOTAL];

// ================= helpers =================
__device__ __forceinline__ uint32_t smem_u32(const void* p){
    uint32_t a;
    asm("{ .reg .u64 t; cvta.to.shared.u64 t, %1; cvt.u32.u64 %0, t; }" : "=r"(a) : "l"(p));
    return a;
}
__device__ __forceinline__ void ldmx4(uint32_t* r, uint32_t a){
    asm volatile("ldmatrix.sync.aligned.m8n8.x4.shared.b16 {%0,%1,%2,%3}, [%4];"
        : "=r"(r[0]),"=r"(r[1]),"=r"(r[2]),"=r"(r[3]) : "r"(a));
}
__device__ __forceinline__ void mma16816(float* d, const uint32_t* a, uint32_t b0, uint32_t b1){
    asm volatile("mma.sync.aligned.m16n8k16.row.col.f32.f16.f16.f32 "
        "{%0,%1,%2,%3}, {%4,%5,%6,%7}, {%8,%9}, {%0,%1,%2,%3};"
        : "+f"(d[0]),"+f"(d[1]),"+f"(d[2]),"+f"(d[3])
        : "r"(a[0]),"r"(a[1]),"r"(a[2]),"r"(a[3]), "r"(b0),"r"(b1));
}
__device__ __forceinline__ void cpasync16(uint32_t dst, const void* src){
    asm volatile("cp.async.cg.shared.global [%0], [%1], 16;" :: "r"(dst), "l"(src));
}
#define CP_COMMIT() asm volatile("cp.async.commit_group;" ::: "memory")
#define CP_WAIT1()  asm volatile("cp.async.wait_group 1;" ::: "memory")
#define CP_WAIT0()  asm volatile("cp.async.wait_group 0;" ::: "memory")

// f32x2 packed fp32 (for lx22 path)
__device__ __forceinline__ unsigned long long pk2(float x) {
    unsigned long long r; unsigned xi = __float_as_uint(x);
    asm("mov.b64 %0, {%1, %1};" : "=l"(r) : "r"(xi));
    return r;
}
__device__ __forceinline__ void fma2(unsigned long long& d, unsigned long long a, unsigned long long b) {
    asm("fma.rn.f32x2 %0, %1, %2, %0;" : "+l"(d) : "l"(a), "l"(b));
}
__device__ __forceinline__ float lo32(unsigned long long v){ return __uint_as_float((unsigned)v); }
__device__ __forceinline__ float hi32(unsigned long long v){ return __uint_as_float((unsigned)(v>>32)); }

// fp16x2 split: x = h0 + h1 + O(2^-22 x)
__device__ __forceinline__ void hsplit(float x, unsigned short& s0, unsigned short& s1)
{
    __half h0 = __float2half_rn(x);
    float r = x - __half2float(h0);
    __half h1 = __float2half_rn(r);
    s0 = __half_as_ushort(h0);
    s1 = __half_as_ushort(h1);
}

// ================= mma.sync fp16x2 GEMM, cp.async double-buffered =================
// C[m][n] = sum_k A[m][k]*B[n][k]; A,B fp16 2-term splits, K-major.
// 128x128 tile, 8 warps (32x64), K-chunk 32, SMEM row stride 40, 2 stages, 2 blocks/SM.
// SPL: 0 none | 2 row-major fp16 splits of output | 3 row-major splits + transposed
//      splits into T0/T1 ([N rows, NN cols] ld NN, batch stride sT) via SMEM staging.
// EPI: 0 C=v | 1 C+=v | 2 C=2v-D | 3 C=exp(2v-D[m]-D[n]) SYMMETRIC + fused rowsum
//      4 C=v+b1[n] | 5 C=relu(v+b1[n]+b2[n]) | 6 C=relu(C+v+b1[n]+b2[n])
// EPI3: S0 reinterpreted as float* rowsum accumulator (pre-zeroed), stride NN per batch.
#define MM_SMEM 81920    // 2 stages * 4 tiles * 5120 * 2B

template<int EPI, int SPL>
__global__ void __launch_bounds__(256, 2)
mma_gemm_k(const hf* __restrict__ A0, const hf* __restrict__ A1,
           const hf* __restrict__ B0, const hf* __restrict__ B1,
           float* __restrict__ C, const float* __restrict__ D,
           const float* __restrict__ bias1, const float* __restrict__ bias2,
           hf* __restrict__ S0, hf* __restrict__ S1,
           hf* __restrict__ T0, hf* __restrict__ T1, long long sT,
           int N, int K, int ldC, int ldD,
           long long sA, long long sB, long long sC, long long sD)
{
    constexpr int STAGE_E = 4*5120;

    if (EPI == 3 && blockIdx.x < blockIdx.y) return;

    extern __shared__ __align__(16) hf sm[];
    const int tid = threadIdx.x;
    const int lane = tid & 31, warp = tid >> 5;
    const int wm = warp >> 1, wn = warp & 1;
    const int bz = blockIdx.z;
    const int row0 = blockIdx.y * 128;
    const int col0 = blockIdx.x * 128;

    const hf* src[4] = { A0 + bz*sA + (long long)row0*K,
                         A1 + bz*sA + (long long)row0*K,
                         B0 + bz*sB + (long long)col0*K,
                         B1 + bz*sB + (long long)col0*K };

    float acc[2][8][4];
#pragma unroll
    for (int i=0;i<2;i++)
#pragma unroll
        for (int j=0;j<8;j++)
#pragma unroll
            for (int u=0;u<4;u++) acc[i][j][u] = 0.f;

    const uint32_t smb = smem_u32(sm);
    const int lrow = lane & 15;
    const int lcol = (lane >> 4) * 8;
    const int r_ld = tid >> 2, q_ld = (tid & 3) * 8;

    auto load_stage = [&](int k0, int st) {
        uint32_t dbase = smb + (uint32_t)st * (STAGE_E*2);
#pragma unroll
        for (int arr = 0; arr < 4; ++arr) {
            const hf* g = src[arr] + k0;
#pragma unroll
            for (int i = 0; i < 2; ++i) {
                int r = r_ld + i*64;
                cpasync16(dbase + (uint32_t)(arr*5120 + r*40 + q_ld)*2,
                          g + (long long)r*K + q_ld);
            }
        }
    };

    const int nk = K >> 5;
    load_stage(0, 0);
    CP_COMMIT();

    for (int it = 0; it < nk; ++it) {
        if (it + 1 < nk) { load_stage((it+1)*32, (it+1)&1); CP_COMMIT(); }
        if (it + 1 < nk) CP_WAIT1(); else CP_WAIT0();
        __syncthreads();

        const uint32_t sb = smb + (uint32_t)(it & 1) * (STAGE_E*2);
#pragma unroll
        for (int ks = 0; ks < 2; ++ks) {
            uint32_t af[2][2][4];
#pragma unroll
            for (int s = 0; s < 2; ++s)
#pragma unroll
                for (int mt = 0; mt < 2; ++mt) {
                    int rr = wm*32 + mt*16 + lrow;
                    ldmx4(af[s][mt], sb + (uint32_t)(s*5120 + rr*40 + ks*16 + lcol)*2);
                }
            uint32_t bfr[2][4][4];
#pragma unroll
            for (int s = 0; s < 2; ++s)
#pragma unroll
                for (int np = 0; np < 4; ++np) {
                    int rr = wn*64 + np*16 + lrow;
                    ldmx4(bfr[s][np], sb + (uint32_t)((2+s)*5120 + rr*40 + ks*16 + lcol)*2);
                }
            const int PA[3] = {0,0,1};
            const int PB[3] = {0,1,0};
#pragma unroll
            for (int p = 0; p < 3; ++p) {
#pragma unroll
                for (int np = 0; np < 4; ++np) {
#pragma unroll
                    for (int mt = 0; mt < 2; ++mt) {
                        mma16816(acc[mt][2*np],   af[PA[p]][mt], bfr[PB[p]][np][0], bfr[PB[p]][np][2]);
                        mma16816(acc[mt][2*np+1], af[PA[p]][mt], bfr[PB[p]][np][1], bfr[PB[p]][np][3]);
                    }
                }
            }
        }
        __syncthreads();
    }

    // ---- epilogue ----
    float* Cb = C + bz*sC;
    const float* Db = D ? D + bz*sD : (const float*)0;

    if (EPI == 3) {
        float* tile = (float*)sm;  // 128 x 129 fp32 = 66048 B <= 81920
#pragma unroll
        for (int mt = 0; mt < 2; ++mt)
#pragma unroll
        for (int h = 0; h < 2; ++h) {
            int lm = wm*32 + mt*16 + (lane >> 2) + h*8;
            int gm = row0 + lm;
#pragma unroll
            for (int nt = 0; nt < 8; ++nt) {
                int ln = wn*64 + nt*8 + (lane & 3)*2;
                int gn = col0 + ln;
                float dm = Db[gm];
                float o0 = expf(2.f*acc[mt][nt][h*2]   - dm - Db[gn]);
                float o1 = expf(2.f*acc[mt][nt][h*2+1] - dm - Db[gn+1]);
                *(float2*)(Cb + (long long)gm*ldC + gn) = make_float2(o0, o1);
                tile[lm*129 + ln]   = o0;
                tile[lm*129 + ln+1] = o1;
            }
        }
        __syncthreads();
        const bool offdiag = (blockIdx.x > blockIdx.y);
        if (offdiag) {
            for (int q = tid; q < 128*128; q += 256) {
                int i = q >> 7, j = q & 127;
                Cb[(long long)(col0 + i)*ldC + row0 + j] = tile[j*129 + i];
            }
        }
        float* dvp = (float*)S0 + (long long)bz*NN;
        if (tid < 128) {
            float s = 0.f;
            const float* tr = tile + tid*129;
#pragma unroll 8
            for (int j = 0; j < 128; ++j) s += tr[j];
            atomicAdd(dvp + row0 + tid, s);
        } else if (offdiag) {
            int t = tid - 128;
            float s = 0.f;
#pragma unroll 8
            for (int j = 0; j < 128; ++j) s += tile[j*129 + t];
            atomicAdd(dvp + col0 + t, s);
        }
        return;
    }

    hf *Sb0 = 0, *Sb1 = 0;
    if (SPL >= 2) { Sb0 = S0 + bz*sC; Sb1 = S1 + bz*sC; }
    float* tile = (float*)sm;   // used only for SPL==3

#pragma unroll
    for (int mt = 0; mt < 2; ++mt)
#pragma unroll
    for (int h = 0; h < 2; ++h) {
        int lm = wm*32 + mt*16 + (lane >> 2) + h*8;
        int gm = row0 + lm;
#pragma unroll
        for (int nt = 0; nt < 8; ++nt) {
            int ln = wn*64 + nt*8 + (lane & 3)*2;
            int gn = col0 + ln;
            float v0 = acc[mt][nt][h*2], v1 = acc[mt][nt][h*2+1];
            long long off = (long long)gm*ldC + gn;
            float* cp = Cb + off;
            float2 o;
            if (EPI == 0)      { o = make_float2(v0, v1); }
            else if (EPI == 1) { float2 c = *(const float2*)cp; o = make_float2(c.x+v0, c.y+v1); }
            else if (EPI == 2) {
                const float2 dd = *(const float2*)(Db + (long long)gm*ldD + gn);
                o = make_float2(2.f*v0 - dd.x, 2.f*v1 - dd.y);
            }
            else if (EPI == 4) { o = make_float2(v0 + bias1[gn], v1 + bias1[gn+1]); }
            else if (EPI == 5) {
                o = make_float2(fmaxf(v0 + bias1[gn]   + bias2[gn],   0.f),
                                fmaxf(v1 + bias1[gn+1] + bias2[gn+1], 0.f));
            }
            else { // 6
                float2 c = *(const float2*)cp;
                o = make_float2(fmaxf(c.x + v0 + bias1[gn]   + bias2[gn],   0.f),
                                fmaxf(c.y + v1 + bias1[gn+1] + bias2[gn+1], 0.f));
            }
            *(float2*)cp = o;
            if (SPL >= 2) {
                unsigned short a0,a1,b0,b1;
                hsplit(o.x,a0,a1); hsplit(o.y,b0,b1);
                *(uint32_t*)(Sb0 + off) = (uint32_t)a0 | ((uint32_t)b0<<16);
                *(uint32_t*)(Sb1 + off) = (uint32_t)a1 | ((uint32_t)b1<<16);
            }
            if (SPL == 3) {
                tile[lm*129 + ln]   = o.x;
                tile[lm*129 + ln+1] = o.y;
            }
        }
    }

    if (SPL == 3) {
        __syncthreads();
        hf* Tb0 = T0 + bz*sT;
        hf* Tb1 = T1 + bz*sT;
        for (int q = tid; q < 128*128; q += 256) {
            int i = q >> 7, j = q & 127;       // i: local col, j: local row
            float v = tile[j*129 + i];
            unsigned short s0,s1;
            hsplit(v,s0,s1);
            long long to = (long long)(col0 + i)*NN + row0 + j;
            Tb0[to] = __ushort_as_half(s0);
            Tb1[to] = __ushort_as_half(s1);
        }
    }
}

// ================= fused elementwise + split kernels =================
__global__ void relu_br_split_k(const float* __restrict__ src, float* __restrict__ dst,
                                const float* __restrict__ br,
                                hf* __restrict__ o0, hf* __restrict__ o1,
                                int total4, int F)
{
    int i = blockIdx.x*blockDim.x + threadIdx.x;
    if (i >= total4) return;
    int f = (i*4) % F;
    float4 v = ((const float4*)src)[i];
    v.x = fmaxf(v.x + br[f],   0.f);
    v.y = fmaxf(v.y + br[f+1], 0.f);
    v.z = fmaxf(v.z + br[f+2], 0.f);
    v.w = fmaxf(v.w + br[f+3], 0.f);
    ((float4*)dst)[i] = v;
    unsigned short a0,a1,b0,b1,c0,c1,d0,d1;
    hsplit(v.x,a0,a1); hsplit(v.y,b0,b1); hsplit(v.z,c0,c1); hsplit(v.w,d0,d1);
    ((uint2*)o0)[i] = make_uint2((uint32_t)a0 | ((uint32_t)b0<<16), (uint32_t)c0 | ((uint32_t)d0<<16));
    ((uint2*)o1)[i] = make_uint2((uint32_t)a1 | ((uint32_t)b1<<16), (uint32_t)c1 | ((uint32_t)d1<<16));
}

// transpose + split
__global__ void tr_split_k(const float* __restrict__ in,
                           hf* __restrict__ o0, hf* __restrict__ o1,
                           int inLd, int outLd, long long inS, long long outS)
{
    __shared__ float t[32][33];
    int r0 = blockIdx.x*32, c0 = blockIdx.y*32;
    const float* ip = in + (long long)blockIdx.z*inS;
    for (int i = threadIdx.y; i < 32; i += 8)
        t[i][threadIdx.x] = ip[(long long)(r0+i)*inLd + c0 + threadIdx.x];
    __syncthreads();
    long long ob = (long long)blockIdx.z*outS;
    for (int i = threadIdx.y; i < 32; i += 8) {
        float x = t[threadIdx.x][i];
        unsigned short s0,s1;
        hsplit(x,s0,s1);
        long long o = ob + (long long)(c0+i)*outLd + r0 + threadIdx.x;
        o0[o] = __ushort_as_half(s0);
        o1[o] = __ushort_as_half(s1);
    }
}

// fused Laplacian normalize + split (2 terms)
__global__ void adjnorm_split_k(const float* __restrict__ adj, const float* __restrict__ dinv,
                                hf* __restrict__ o0, hf* __restrict__ o1)
{
    long long i4 = (long long)blockIdx.x*blockDim.x + threadIdx.x;
    long long tot4 = (long long)BB*NN*NN/4;
    if (i4 >= tot4) return;
    long long bse = i4*4;
    int c = (int)(bse % NN);
    long long row = bse / NN;
    int r = (int)(row % NN);
    float dr = dinv[row];
    const float* dc = dinv + (row - r);
    float4 v = ((const float4*)adj)[i4];
    float w[4];
    w[0] = v.x*dr*dc[c];   w[1] = v.y*dr*dc[c+1];
    w[2] = v.z*dr*dc[c+2]; w[3] = v.w*dr*dc[c+3];
#pragma unroll
    for (int u=0;u<4;u++) w[u] = (r == c+u) ? (1.f - w[u]) : (-w[u]);
    unsigned short a0,a1,b0,b1,c0s,c1s,d0,d1;
    hsplit(w[0],a0,a1); hsplit(w[1],b0,b1); hsplit(w[2],c0s,c1s); hsplit(w[3],d0,d1);
    ((uint2*)o0)[i4] = make_uint2((uint32_t)a0 | ((uint32_t)b0<<16), (uint32_t)c0s | ((uint32_t)d0<<16));
    ((uint2*)o1)[i4] = make_uint2((uint32_t)a1 | ((uint32_t)b1<<16), (uint32_t)c1s | ((uint32_t)d1<<16));
}

__global__ void zero_k(float* __restrict__ p, int n)
{
    int i = blockIdx.x*blockDim.x + threadIdx.x;
    if (i < n) p[i] = 0.f;
}
__global__ void rsqrt_k(float* __restrict__ p, int n)
{
    int i = blockIdx.x*blockDim.x + threadIdx.x;
    if (i < n) p[i] = rsqrtf(p[i]);
}
__global__ void zero_h_k(hf* __restrict__ p, long long n4)
{
    long long i = (long long)blockIdx.x*blockDim.x + threadIdx.x;
    if (i < n4) ((uint2*)p)[i] = make_uint2(0u, 0u);
}

// pad x [rows,6] -> splits [rows,32] (cols 6..31 zero)
__global__ void xpad_split_k(const float* __restrict__ x, hf* __restrict__ o0, hf* __restrict__ o1)
{
    int row = blockIdx.x*blockDim.x + threadIdx.x;
    if (row >= BB*NN) return;
    const float* xr = x + (long long)row*6;
    hf* p0 = o0 + (long long)row*32;
    hf* p1 = o1 + (long long)row*32;
#pragma unroll
    for (int c = 0; c < 6; ++c) {
        unsigned short s0,s1;
        hsplit(xr[c], s0, s1);
        p0[c] = __ushort_as_half(s0);
        p1[c] = __ushort_as_half(s1);
    }
#pragma unroll
    for (int c = 6; c < 32; ++c) { p0[c] = __ushort_as_half(0); p1[c] = __ushort_as_half(0); }
}

// W0 [6][22][128] -> padded splits [128 rows, 192 K]
__global__ void w0pad_split_k(const float* __restrict__ W, hf* __restrict__ o0, hf* __restrict__ o1)
{
    int idx = blockIdx.x*blockDim.x + threadIdx.x;
    if (idx >= 128*192) return;
    int n = idx / 192, kc = idx % 192;
    int k = kc >> 5, c = kc & 31;
    float v = (c < 22) ? W[((long long)k*22 + c)*128 + n] : 0.f;
    unsigned short s0,s1;
    hsplit(v, s0, s1);
    o0[idx] = __ushort_as_half(s0);
    o1[idx] = __ushort_as_half(s1);
}

// ================= narrow L@T (cin=22) symmetric split-K =================
__global__ void __launch_bounds__(256)
lx_part_k(const float* __restrict__ L, const float* __restrict__ T, float* __restrict__ part)
{
    const int b = blockIdx.z;
    const int s = blockIdx.y;
    const int r0 = blockIdx.x * 512 + threadIdx.x * 2;
    const float* Lb = L + (long long)b*NN*NN;
    const float* Tp = T + (long long)b*NN*22;
    __shared__ float Tsh[32][24];
    unsigned long long accA[11], accB[11];
#pragma unroll
    for (int j=0;j<11;j++){ accA[j]=0ull; accB[j]=0ull; }
    const int kbeg = s * (NN/NSPLIT);
    const int kend = kbeg + (NN/NSPLIT);
    for (int k0 = kbeg; k0 < kend; k0 += 32) {
        for (int idx = threadIdx.x; idx < 32*22; idx += 256) {
            int kk = idx / 22, c = idx % 22;
            Tsh[kk][c] = Tp[(long long)(k0+kk)*22 + c];
        }
        __syncthreads();
#pragma unroll
        for (int kk = 0; kk < 32; ++kk) {
            float2 l2 = *(const float2*)(Lb + (long long)(k0+kk)*NN + r0);
            unsigned long long lx = pk2(l2.x), ly = pk2(l2.y);
#pragma unroll
            for (int j=0;j<11;j++) {
                unsigned long long tp = *(const unsigned long long*)&Tsh[kk][2*j];
                fma2(accA[j], lx, tp);
                fma2(accB[j], ly, tp);
            }
        }
        __syncthreads();
    }
    float* p = part + ((long long)(s*BB + b)*NN)*24;
#pragma unroll
    for (int j=0;j<11;j++) {
        p[(long long)r0*24     + 2*j]   = lo32(accA[j]);
        p[(long long)r0*24     + 2*j+1] = hi32(accA[j]);
        p[(long long)(r0+1)*24 + 2*j]   = lo32(accB[j]);
        p[(long long)(r0+1)*24 + 2*j+1] = hi32(accB[j]);
    }
}

// reduce + write T fp32 (22-col) + fused fp16 splits into stacked slot (ld 192)
__global__ void lx_reduce_k(const float* __restrict__ part, float* __restrict__ Tout,
                            const float* __restrict__ Tprev, int mode,
                            hf* __restrict__ s0, hf* __restrict__ s1, int slotoff)
{
    int idx = blockIdx.x*blockDim.x + threadIdx.x;
    if (idx >= BB*NN*22) return;
    int c   = idx % 22;
    int row = idx / 22;
    float s = 0.f;
#pragma unroll
    for (int k=0;k<NSPLIT;k++)
        s += part[((long long)k*BB*NN + row)*24 + c];
    float v = (mode == 2) ? (2.f*s - Tprev[(long long)row*22 + c]) : s;
    Tout[(long long)row*22 + c] = v;
    unsigned short a0,a1;
    hsplit(v,a0,a1);
    long long so = (long long)row*192 + slotoff + c;
    s0[so] = __ushort_as_half(a0);
    s1[so] = __ushort_as_half(a1);
}

// ================= elementwise / reductions =================
__global__ void concat_input_k(const float* __restrict__ x, const int* __restrict__ cat,
                               float* __restrict__ X0, hf* __restrict__ s0, hf* __restrict__ s1)
{
    int idx = blockIdx.x*blockDim.x + threadIdx.x;
    if (idx >= BB*NN) return;
    int b = idx / NN;
    float* o = X0 + (long long)idx*22;
    hf* p0 = s0 + (long long)idx*192;
    hf* p1 = s1 + (long long)idx*192;
    const float* xi = x + (long long)idx*6;
    int c = cat[b];
#pragma unroll
    for (int i=0;i<22;i++) {
        float v = (i < 6) ? xi[i] : ((i-6)==c ? 1.f : 0.f);
        o[i] = v;
        unsigned short h0,h1;
        hsplit(v,h0,h1);
        p0[i] = __ushort_as_half(h0);
        p1[i] = __ushort_as_half(h1);
    }
}

__device__ __forceinline__ float block_reduce_sum(float v)
{
    __shared__ float s[32];
    int lane = threadIdx.x & 31, wid = threadIdx.x >> 5;
#pragma unroll
    for (int o=16;o>0;o>>=1) v += __shfl_down_sync(0xffffffffu, v, o);
    if (lane == 0) s[wid] = v;
    __syncthreads();
    int nw = blockDim.x >> 5;
    v = (threadIdx.x < nw) ? s[threadIdx.x] : 0.f;
    if (wid == 0) {
#pragma unroll
        for (int o=16;o>0;o>>=1) v += __shfl_down_sync(0xffffffffu, v, o);
    }
    return v;
}

__global__ void row_sq_k(const float* __restrict__ X, float* __restrict__ sq, int F)
{
    const float* r = X + (long long)blockIdx.x * F;
    float s = 0.f;
    for (int i = threadIdx.x; i < F; i += blockDim.x) { float v = r[i]; s += v*v; }
    s = block_reduce_sum(s);
    if (threadIdx.x == 0) sq[blockIdx.x] = s;
}

__global__ void row_sq_v4_k(const float* __restrict__ X, float* __restrict__ sq, int F4)
{
    const float4* r = (const float4*)X + (long long)blockIdx.x * F4;
    float s = 0.f;
    for (int i = threadIdx.x; i < F4; i += blockDim.x) {
        float4 v = r[i];
        s += v.x*v.x + v.y*v.y + v.z*v.z + v.w*v.w;
    }
    s = block_reduce_sum(s);
    if (threadIdx.x == 0) sq[blockIdx.x] = s;
}

__global__ void normalize_v4_k(float* __restrict__ L, const float* __restrict__ dinv)
{
    long long i4 = (long long)blockIdx.x*blockDim.x + threadIdx.x;
    long long tot4 = (long long)BB*NN*NN/4;
    if (i4 >= tot4) return;
    long long base = i4*4;
    int c = (int)(base % NN);
    long long row = base / NN;
    int r = (int)(row % NN);
    float dr = dinv[row];
    const float* dc = dinv + (row - r);
    float4 v = ((const float4*)L)[i4];
    v.x *= dr*dc[c];   v.y *= dr*dc[c+1];
    v.z *= dr*dc[c+2]; v.w *= dr*dc[c+3];
    float4 o;
    o.x = (r==c  ) ? 1.f-v.x : -v.x;
    o.y = (r==c+1) ? 1.f-v.y : -v.y;
    o.z = (r==c+2) ? 1.f-v.z : -v.z;
    o.w = (r==c+3) ? 1.f-v.w : -v.w;
    ((float4*)L)[i4] = o;
}

__global__ void relu_2b_k(float* __restrict__ p, const float* __restrict__ b1,
                          const float* __restrict__ b2, int total, int F)
{
    int i = blockIdx.x*blockDim.x + threadIdx.x;
    if (i < total) { int f = i % F; p[i] = fmaxf(p[i] + b1[f] + b2[f], 0.f); }
}

// ================= legacy fp32 tiled SGEMM (FC2 only) =================
template<int BM,int BN,int BK,int TM,int TN,int MODE,bool TB>
__global__ void __launch_bounds__((BM/TM)*(BN/TN))
gemm_k(const float* __restrict__ A, const float* __restrict__ Bm,
       float* C, const float* D,
       int M, int N, int K,
       long long sA, long long sB, long long sC, long long sD)
{
    constexpr int NT = (BM/TM)*(BN/TN);
    const int bz = blockIdx.z;
    A  += (long long)bz * sA;
    Bm += (long long)bz * sB;
    C  += (long long)bz * sC;
    if (D) D += (long long)bz * sD;
    const int row0 = blockIdx.y * BM;
    const int col0 = blockIdx.x * BN;
    __shared__ float As[BK][BM+4];
    __shared__ float Bs[BK][BN+4];
    const int tid = threadIdx.x;
    const int tx  = tid % (BN/TN);
    const int ty  = tid / (BN/TN);
    float acc[TM][TN];
#pragma unroll
    for (int i=0;i<TM;i++)
#pragma unroll
        for (int j=0;j<TN;j++) acc[i][j] = 0.f;
    for (int k0 = 0; k0 < K; k0 += BK) {
#pragma unroll
        for (int idx = tid; idx < BM*BK; idx += NT) {
            int m  = idx / BK, kk = idx % BK;
            int gm = row0 + m, gk = k0 + kk;
            As[kk][m] = (gm < M && gk < K) ? A[(long long)gm*K + gk] : 0.f;
        }
        if (TB) {
#pragma unroll
            for (int idx = tid; idx < BK*BN; idx += NT) {
                int n  = idx / BK, kk = idx % BK;
                int gn = col0 + n, gk = k0 + kk;
                Bs[kk][n] = (gn < N && gk < K) ? Bm[(long long)gn*K + gk] : 0.f;
            }
        } else {
#pragma unroll
            for (int idx = tid; idx < BK*BN; idx += NT) {
                int kk = idx / BN, n = idx % BN;
                int gk = k0 + kk, gn = col0 + n;
                Bs[kk][n] = (gk < K && gn < N) ? Bm[(long long)gk*N + gn] : 0.f;
            }
        }
        __syncthreads();
#pragma unroll
        for (int kk = 0; kk < BK; ++kk) {
            float a[TM], b[TN];
#pragma unroll
            for (int i=0;i<TM;++i) a[i] = As[kk][ty*TM + i];
#pragma unroll
            for (int j=0;j<TN;++j) b[j] = Bs[kk][tx*TN + j];
#pragma unroll
            for (int i=0;i<TM;++i)
#pragma unroll
                for (int j=0;j<TN;++j)
                    acc[i][j] = fmaf(a[i], b[j], acc[i][j]);
        }
        __syncthreads();
    }
#pragma unroll
    for (int i=0;i<TM;++i) {
        int gm = row0 + ty*TM + i;
        if (gm >= M) continue;
#pragma unroll
        for (int j=0;j<TN;++j) {
            int gn = col0 + tx*TN + j;
            if (gn >= N) continue;
            long long off = (long long)gm*N + gn;
            float v = acc[i][j];
            if (MODE == 0)      C[off] = v;
            else if (MODE == 1) C[off] += v;
            else                C[off] = expf(2.f*v - D[gm] - D[gn]);
        }
    }
}

// ================= host helpers =================
static inline void gemm_big(int mode, const float* A, const float* B, float* C, const float* D,
                            int M, int N, int K, int batch,
                            long long sA, long long sB, long long sC, long long sD)
{
    dim3 g((N+63)/64, (M+127)/128, batch);
    switch (mode) {
      case 0: gemm_k<128,64,16,8,4,0,false><<<g,256>>>(A,B,C,D,M,N,K,sA,sB,sC,sD); break;
      case 1: gemm_k<128,64,16,8,4,1,false><<<g,256>>>(A,B,C,D,M,N,K,sA,sB,sC,sD); break;
    }
}

static inline void tc_gemm(int epi, int spl, hf* const* As, hf* const* Bs,
                           float* C, const float* D, const float* b1, const float* b2,
                           hf* s0, hf* s1,
                           int Mb, int N, int K, int ldC, int ldD, int batch,
                           long long sA, long long sB, long long sC, long long sD,
                           hf* t0 = 0, hf* t1 = 0, long long sT = 0)
{
    dim3 g(N/128, Mb/128, batch);
    switch (epi*10 + spl) {
      case 0:  mma_gemm_k<0,0><<<g,256,MM_SMEM>>>(As[0],As[1],Bs[0],Bs[1],C,D,b1,b2,s0,s1,t0,t1,sT,N,K,ldC,ldD,sA,sB,sC,sD); break;
      case 2:  mma_gemm_k<0,2><<<g,256,MM_SMEM>>>(As[0],As[1],Bs[0],Bs[1],C,D,b1,b2,s0,s1,t0,t1,sT,N,K,ldC,ldD,sA,sB,sC,sD); break;
      case 3:  mma_gemm_k<0,3><<<g,256,MM_SMEM>>>(As[0],As[1],Bs[0],Bs[1],C,D,b1,b2,s0,s1,t0,t1,sT,N,K,ldC,ldD,sA,sB,sC,sD); break;
      case 10: mma_gemm_k<1,0><<<g,256,MM_SMEM>>>(As[0],As[1],Bs[0],Bs[1],C,D,b1,b2,s0,s1,t0,t1,sT,N,K,ldC,ldD,sA,sB,sC,sD); break;
      case 12: mma_gemm_k<1,2><<<g,256,MM_SMEM>>>(As[0],As[1],Bs[0],Bs[1],C,D,b1,b2,s0,s1,t0,t1,sT,N,K,ldC,ldD,sA,sB,sC,sD); break;
      case 22: mma_gemm_k<2,2><<<g,256,MM_SMEM>>>(As[0],As[1],Bs[0],Bs[1],C,D,b1,b2,s0,s1,t0,t1,sT,N,K,ldC,ldD,sA,sB,sC,sD); break;
      case 23: mma_gemm_k<2,3><<<g,256,MM_SMEM>>>(As[0],As[1],Bs[0],Bs[1],C,D,b1,b2,s0,s1,t0,t1,sT,N,K,ldC,ldD,sA,sB,sC,sD); break;
      case 30: mma_gemm_k<3,0><<<g,256,MM_SMEM>>>(As[0],As[1],Bs[0],Bs[1],C,D,b1,b2,s0,s1,t0,t1,sT,N,K,ldC,ldD,sA,sB,sC,sD); break;
      case 40: mma_gemm_k<4,0><<<g,256,MM_SMEM>>>(As[0],As[1],Bs[0],Bs[1],C,D,b1,b2,s0,s1,t0,t1,sT,N,K,ldC,ldD,sA,sB,sC,sD); break;
      case 42: mma_gemm_k<4,2><<<g,256,MM_SMEM>>>(As[0],As[1],Bs[0],Bs[1],C,D,b1,b2,s0,s1,t0,t1,sT,N,K,ldC,ldD,sA,sB,sC,sD); break;
      case 52: mma_gemm_k<5,2><<<g,256,MM_SMEM>>>(As[0],As[1],Bs[0],Bs[1],C,D,b1,b2,s0,s1,t0,t1,sT,N,K,ldC,ldD,sA,sB,sC,sD); break;
      case 60: mma_gemm_k<6,0><<<g,256,MM_SMEM>>>(As[0],As[1],Bs[0],Bs[1],C,D,b1,b2,s0,s1,t0,t1,sT,N,K,ldC,ldD,sA,sB,sC,sD); break;
    }
}

extern "C" void kernel_launch(void* const* d_in, const int* in_sizes, int n_in,
                              void* d_out, int out_size)
{
    (void)in_sizes; (void)n_in; (void)out_size;

    cudaFuncSetAttribute(mma_gemm_k<0,0>, cudaFuncAttributeMaxDynamicSharedMemorySize, MM_SMEM);
    cudaFuncSetAttribute(mma_gemm_k<0,2>, cudaFuncAttributeMaxDynamicSharedMemorySize, MM_SMEM);
    cudaFuncSetAttribute(mma_gemm_k<0,3>, cudaFuncAttributeMaxDynamicSharedMemorySize, MM_SMEM);
    cudaFuncSetAttribute(mma_gemm_k<1,0>, cudaFuncAttributeMaxDynamicSharedMemorySize, MM_SMEM);
    cudaFuncSetAttribute(mma_gemm_k<1,2>, cudaFuncAttributeMaxDynamicSharedMemorySize, MM_SMEM);
    cudaFuncSetAttribute(mma_gemm_k<2,2>, cudaFuncAttributeMaxDynamicSharedMemorySize, MM_SMEM);
    cudaFuncSetAttribute(mma_gemm_k<2,3>, cudaFuncAttributeMaxDynamicSharedMemorySize, MM_SMEM);
    cudaFuncSetAttribute(mma_gemm_k<3,0>, cudaFuncAttributeMaxDynamicSharedMemorySize, MM_SMEM);
    cudaFuncSetAttribute(mma_gemm_k<4,0>, cudaFuncAttributeMaxDynamicSharedMemorySize, MM_SMEM);
    cudaFuncSetAttribute(mma_gemm_k<4,2>, cudaFuncAttributeMaxDynamicSharedMemorySize, MM_SMEM);
    cudaFuncSetAttribute(mma_gemm_k<5,2>, cudaFuncAttributeMaxDynamicSharedMemorySize, MM_SMEM);
    cudaFuncSetAttribute(mma_gemm_k<6,0>, cudaFuncAttributeMaxDynamicSharedMemorySize, MM_SMEM);

    const float* x   = (const float*)d_in[0];
    const int*   cat = (const int*)  d_in[1];
    const float* Wc[3] = {(const float*)d_in[2], (const float*)d_in[4], (const float*)d_in[6]};
    const float* bc[3] = {(const float*)d_in[3], (const float*)d_in[5], (const float*)d_in[7]};
    const float* fw[3] = {(const float*)d_in[8], (const float*)d_in[10], (const float*)d_in[12]};
    const float* fb[3] = {(const float*)d_in[9], (const float*)d_in[11], (const float*)d_in[13]};
    const float* br[6];
    for (int i=0;i<6;i++) br[i] = (const float*)d_in[14+i];
    float* out = (float*)d_out;

    float *L,*sqv,*dv,*X0,*Ta,*Tb,*pre,*act0,*skip,*act2,*fc0,*fc1,*part;
    cudaGetSymbolAddress((void**)&L,   g_L);
    cudaGetSymbolAddress((void**)&sqv, g_sq);
    cudaGetSymbolAddress((void**)&dv,  g_dinv);
    cudaGetSymbolAddress((void**)&X0,  g_X0);
    cudaGetSymbolAddress((void**)&Ta,  g_Ta);
    cudaGetSymbolAddress((void**)&Tb,  g_Tb);
    cudaGetSymbolAddress((void**)&pre, g_pre);
    cudaGetSymbolAddress((void**)&act0,g_act0);
    cudaGetSymbolAddress((void**)&skip,g_skip);
    cudaGetSymbolAddress((void**)&act2,g_act2);
    cudaGetSymbolAddress((void**)&fc0, g_fc0);
    cudaGetSymbolAddress((void**)&fc1, g_fc1);
    cudaGetSymbolAddress((void**)&part,g_part);

    hf *LS[2], *RS[2], *TS[2], *SK[2], *WT[2];
    cudaGetSymbolAddress((void**)&LS[0], g_LS0); cudaGetSymbolAddress((void**)&LS[1], g_LS1);
    cudaGetSymbolAddress((void**)&RS[0], g_RS0); cudaGetSymbolAddress((void**)&RS[1], g_RS1);
    cudaGetSymbolAddress((void**)&TS[0], g_TS0); cudaGetSymbolAddress((void**)&TS[1], g_TS1);
    cudaGetSymbolAddress((void**)&SK[0], g_SK0); cudaGetSymbolAddress((void**)&SK[1], g_SK1);
    cudaGetSymbolAddress((void**)&WT[0], g_WT0); cudaGetSymbolAddress((void**)&WT[1], g_WT1);

    const long long sL = (long long)NN*NN;
    const long long tot4 = (long long)BB*NN*NN/4;
    const long long preoff = (long long)BB*NN*512;   // pre-splits region inside RS

    // weight layout in WT (transposed [out,in], K-major)
    const long long oW1a = 0;
    const long long oW1s = oW1a + 512LL*128;
    const long long oW2a = oW1s + 512LL*512;
    const long long oW2s = oW2a + 1024LL*512;
    const long long oF0  = oW2s + 1024LL*1024;
    const long long oF1a = oF0  + 512LL*1024;
    const long long oF1b = oF1a + 128LL*512;
    const long long oW0  = oF1b + 128LL*512;         // W0 padded [128, 192]

    {   dim3 g(128/32, 512/32, 1);
        tr_split_k<<<g,dim3(32,8)>>>(Wc[1], WT[0]+oW1a, WT[1]+oW1a, 512, 128, 0, 0); }
    {   dim3 g(128/32, 512/32, 4);
        tr_split_k<<<g,dim3(32,8)>>>(Wc[1]+128LL*512, WT[0]+oW1s, WT[1]+oW1s,
                                     512, 512, 128LL*512, 128); }
    {   dim3 g(512/32, 1024/32, 1);
        tr_split_k<<<g,dim3(32,8)>>>(Wc[2], WT[0]+oW2a, WT[1]+oW2a, 1024, 512, 0, 0); }
    {   dim3 g(512/32, 1024/32, 2);
        tr_split_k<<<g,dim3(32,8)>>>(Wc[2]+512LL*1024, WT[0]+oW2s, WT[1]+oW2s,
                                     1024, 1024, 512LL*1024, 512); }
    {   dim3 g(1024/32, 512/32, 1);
        tr_split_k<<<g,dim3(32,8)>>>(fw[0], WT[0]+oF0, WT[1]+oF0, 512, 1024, 0, 0); }
    {   dim3 g(512/32, 128/32, 1);
        tr_split_k<<<g,dim3(32,8)>>>(fw[1],           WT[0]+oF1a, WT[1]+oF1a, 128, 512, 0, 0);
        tr_split_k<<<g,dim3(32,8)>>>(fw[1]+512LL*128, WT[0]+oF1b, WT[1]+oF1b, 128, 512, 0, 0); }
    w0pad_split_k<<<(128*192+255)/256,256>>>(Wc[0], WT[0]+oW0, WT[1]+oW0);

    auto wp = [&](long long off){ static hf* tmp[2]; tmp[0]=WT[0]+off; tmp[1]=WT[1]+off; return (hf* const*)tmp; };

    auto laplacian_tc = [&](const float* feat, int F, hf* f0, hf* f1) {
        row_sq_v4_k<<<BB*NN,128>>>(feat, sqv, F/4);
        zero_k<<<(BB*NN+255)/256,256>>>(dv, BB*NN);
        hf* FS[2] = {f0, f1};
        tc_gemm(3, 0, FS, FS, L, sqv, 0, 0, (hf*)dv, 0, NN, NN, F, NN, 0, BB,
                (long long)NN*F, (long long)NN*F, sL, NN);
        rsqrt_k<<<(BB*NN+255)/256,256>>>(dv, BB*NN);
        adjnorm_split_k<<<(unsigned)((tot4+255)/256),256>>>(L, dv, LS[0], LS[1]);
    };

    auto split_tr = [&](const float* src, int cin, int inLd) {
        dim3 g(NN/32, cin/32, BB);
        tr_split_k<<<g,dim3(32,8)>>>(src, TS[0], TS[1], inLd, NN,
                                     (long long)NN*inLd, (long long)cin*NN);
    };

    auto lx22 = [&](int mode, const float* Tin, float* Tout, const float* Tprev, int slot) {
        dim3 g(NN/512, NSPLIT, BB);
        lx_part_k<<<g,256>>>(L, Tin, part);
        lx_reduce_k<<<(BB*NN*22+255)/256,256>>>(part, Tout, Tprev, mode, RS[0], RS[1], slot*32);
    };

    // ---- input assembly + stacked-T0 splits; F=6 Laplacian via tensor path ----
    zero_h_k<<<(unsigned)(((long long)BB*NN*192/4+255)/256),256>>>(RS[0], (long long)BB*NN*192/4);
    zero_h_k<<<(unsigned)(((long long)BB*NN*192/4+255)/256),256>>>(RS[1], (long long)BB*NN*192/4);
    concat_input_k<<<(BB*NN+127)/128,128>>>(x, cat, X0, RS[0], RS[1]);
    xpad_split_k<<<(BB*NN+127)/128,128>>>(x, SK[0], SK[1]);
    {
        row_sq_k<<<BB*NN,64>>>(x, sqv, 6);
        zero_k<<<(BB*NN+255)/256,256>>>(dv, BB*NN);
        tc_gemm(3, 0, SK, SK, L, sqv, 0, 0, (hf*)dv, 0, NN, NN, 32, NN, 0, BB,
                (long long)NN*32, (long long)NN*32, sL, NN);
        rsqrt_k<<<(BB*NN+255)/256,256>>>(dv, BB*NN);
        normalize_v4_k<<<(unsigned)((tot4+255)/256),256>>>(L, dv);   // fp32 L for lx22
    }

    // ---- conv 0: cheb recursion (fp32) with fused stacked splits; ONE T@W GEMM K=192 ----
    {
        lx22(0, X0, Ta, nullptr, 1);
        const float* Tprev = X0; float* Tcur = Ta;
        for (int k = 2; k < 6; ++k) {
            float* Tnext = (Tprev == X0) ? Tb : (float*)Tprev;
            lx22(2, Tcur, Tnext, Tprev, k);
            Tprev = Tcur; Tcur = Tnext;
        }
        tc_gemm(4, 2, RS, wp(oW0), pre, 0, bc[0], 0, RS[0]+preoff, RS[1]+preoff,
                BB*NN, 128, 192, 128, 0, 1, 0,0,0,0);
    }

    // ---- Laplacian #2 (F=128) ----
    laplacian_tc(pre, 128, RS[0]+preoff, RS[1]+preoff);
    relu_br_split_k<<<(BB*NN*128/4+255)/256,256>>>(pre, act0, br[0], SK[0], SK[1], BB*NN*128/4, 128);

    // ---- conv 1: cin=128 -> 512, K=5; T1..T4 stacked in Tb [M,512]; SPL3 fuses transposed splits ----
    {
        const int cin = 128;
        const long long sTall = (long long)NN*512;
        const long long sTS = (long long)cin*NN;
        split_tr(act0, cin, cin);
        tc_gemm(4, 0, SK, wp(oW1a), pre, 0, bc[1], 0, 0,0, BB*NN, 512, cin, 512, 0, 1, 0,0,0,0);
        // T1: row splits into RS + transposed splits into TS (for next GEMM)
        tc_gemm(0, 3, LS, TS, Tb, 0, 0, 0, RS[0], RS[1], NN, cin, NN, 512, 0, BB,
                sL, sTS, sTall, 0, TS[0], TS[1], sTS);
        // T2 = 2 L@T1 - act0
        tc_gemm(2, 3, LS, TS, Tb + 128, act0, 0, 0, RS[0]+128, RS[1]+128, NN, cin, NN, 512, cin, BB,
                sL, sTS, sTall, (long long)NN*cin, TS[0], TS[1], sTS);
        // T3 = 2 L@T2 - T1
        tc_gemm(2, 3, LS, TS, Tb + 256, Tb + 0, 0, 0, RS[0]+256, RS[1]+256, NN, cin, NN, 512, 512, BB,
                sL, sTS, sTall, sTall, TS[0], TS[1], sTS);
        // T4 = 2 L@T3 - T2 (row splits only)
        tc_gemm(2, 2, LS, TS, Tb + 384, Tb + 128, 0, 0, RS[0]+384, RS[1]+384, NN, cin, NN, 512, 512, BB,
                sL, sTS, sTall, sTall);
        // batched T@W (K=512) -> pre, emit pre splits for Laplacian #3
        tc_gemm(1, 2, RS, wp(oW1s), pre, 0, 0, 0, RS[0]+preoff, RS[1]+preoff,
                BB*NN, 512, 512, 512, 0, 1, 0,0,0,0);
    }

    // ---- Laplacian #3 (F=512) ----
    laplacian_tc(pre, 512, RS[0]+preoff, RS[1]+preoff);
    relu_br_split_k<<<(BB*NN*512/4+255)/256,256>>>(pre, skip, br[1], SK[0], SK[1], BB*NN*512/4, 512);

    // ---- conv 2: cin=512 -> 1024, K=3; T1..T2 stacked in act2 [M,1024]; SPL3 on T1 ----
    {
        const int cin = 512;
        const long long sTall = (long long)NN*1024;
        const long long sTS = (long long)cin*NN;
        split_tr(skip, cin, cin);
        tc_gemm(4, 0, SK, wp(oW2a), pre, 0, bc[2], 0, 0,0, BB*NN, 1024, cin, 1024, 0, 1, 0,0,0,0);
        // T1: row splits + transposed splits (for T2's GEMM)
        tc_gemm(0, 3, LS, TS, act2, 0, 0, 0, RS[0], RS[1], NN, cin, NN, 1024, 0, BB,
                sL, sTS, sTall, 0, TS[0], TS[1], sTS);
        // T2 = 2 L@T1 - skip (row splits only)
        tc_gemm(2, 2, LS, TS, act2 + 512, skip, 0, 0, RS[0]+512, RS[1]+512, NN, cin, NN, 1024, cin, BB,
                sL, sTS, sTall, (long long)NN*cin);
        tc_gemm(1, 0, RS, wp(oW2s), pre, 0, 0, 0, 0,0, BB*NN, 1024, 1024, 1024, 0, 1, 0,0,0,0);
    }
    relu_br_split_k<<<(BB*NN*1024/4+255)/256,256>>>(pre, act2, br[2], RS[0], RS[1], BB*NN*1024/4, 1024);

    // ---- FC0: 1024 -> 512, fused bias+br+relu; emit fc0 splits into TS ----
    tc_gemm(5, 2, RS, wp(oF0), fc0, 0, fb[0], br[3], TS[0], TS[1], BB*NN, 512, 1024, 512, 0, 1, 0,0,0,0);

    // ---- FC1: concat(fc0, skip) -> 128 ----
    tc_gemm(0, 0, TS, wp(oF1a), fc1, 0, 0, 0, 0,0, BB*NN, 128, 512, 128, 0, 1, 0,0,0,0);
    tc_gemm(6, 0, SK, wp(oF1b), fc1, 0, fb[1], br[4], 0,0, BB*NN, 128, 512, 128, 0, 1, 0,0,0,0);

    // ---- FC2: 128 -> 50 (fp32 path) ----
    gemm_big(0, fc1, fw[2], out, nullptr, BB*NN, 50, 128, 1, 0,0,0,0);
    relu_2b_k<<<(BB*NN*50+255)/256,256>>>(out, fb[2], br[5], BB*NN*50, 50);
}